// round 1
// baseline (speedup 1.0000x reference)
#include <cuda_runtime.h>
#include <cuda_bf16.h>

// Problem shape (fixed by dataset): B=16, S=1024, D=1024, A=256
#define B_    16
#define S_    1024
#define D_    1024
#define A_    256
#define NSEG  16
#define SEGL  64      // S_/NSEG

// ---------------- scratch (device globals; no allocation allowed) -------------
__device__ float g_spart[2 * B_ * S_];       // per-col-block partial scores [2][16384]
__device__ float g_w [B_ * S_];              // exp(s - max_b)
__device__ float g_zp[B_ * S_];              // inclusive prefix sum of w
__device__ float g_zs[B_ * S_];              // inclusive suffix sum of w
__device__ float g_ps[B_ * NSEG * D_];       // segment partial sums of w*h

// ---------------- small float4 helpers ----------------------------------------
__device__ __forceinline__ float4 f4add(float4 a, float4 b) {
    return make_float4(a.x + b.x, a.y + b.y, a.z + b.z, a.w + b.w);
}
__device__ __forceinline__ float4 f4fma(float s, float4 h, float4 acc) {
    acc.x = fmaf(s, h.x, acc.x); acc.y = fmaf(s, h.y, acc.y);
    acc.z = fmaf(s, h.z, acc.z); acc.w = fmaf(s, h.w, acc.w);
    return acc;
}
__device__ __forceinline__ float4 f4scale(float4 a, float s) {
    return make_float4(a.x * s, a.y * s, a.z * s, a.w * s);
}

// ==============================================================================
// K1: scores GEMM.  z = hidden(16384x1024) @ W1(1024x256); s_row = sum_a v[a]*tanh(z+b1)
// 128x128 block tile, 8x8 thread tile, BK=16, double-buffered smem.
// gridDim = (128, 2). Each (block, row) writes ONE partial (no atomics).
// ==============================================================================
#define BM 128
#define BN 128
#define BK 16

__global__ __launch_bounds__(256, 1)
void k_scores(const float* __restrict__ H, const float* __restrict__ W1,
              const float* __restrict__ b1, const float* __restrict__ v)
{
    __shared__ float As[2][BK][BM];   // [k][m]  (transposed A tile)
    __shared__ float Bs[2][BK][BN];   // [k][n]

    const int tid = threadIdx.x;
    const int m0  = blockIdx.x * BM;
    const int n0  = blockIdx.y * BN;

    // A load mapping: 4 threads per row (16 floats of K per tile), 2 rows per thread
    const int arow = tid >> 2;           // 0..63 (and +64)
    const int akq  = (tid & 3) * 4;      // k offset within tile: 0,4,8,12
    // B load mapping: 2 float4 per thread
    const int bk0  = tid >> 5;           // 0..7 (and +8)
    const int bc   = (tid & 31) * 4;     // 0..124

    const int tx = tid & 15;             // col group
    const int ty = tid >> 4;             // row group

    const float* Ap = H  + (size_t)m0 * D_;
    const float* Bp = W1 + n0;

    float acc[8][8];
#pragma unroll
    for (int i = 0; i < 8; i++)
#pragma unroll
        for (int j = 0; j < 8; j++) acc[i][j] = 0.f;

    // prologue: fill stage 0
    {
        float4 a0 = *reinterpret_cast<const float4*>(Ap + (size_t)arow * D_        + akq);
        float4 a1 = *reinterpret_cast<const float4*>(Ap + (size_t)(arow + 64) * D_ + akq);
        As[0][akq + 0][arow] = a0.x; As[0][akq + 1][arow] = a0.y;
        As[0][akq + 2][arow] = a0.z; As[0][akq + 3][arow] = a0.w;
        As[0][akq + 0][arow + 64] = a1.x; As[0][akq + 1][arow + 64] = a1.y;
        As[0][akq + 2][arow + 64] = a1.z; As[0][akq + 3][arow + 64] = a1.w;
        float4 b0 = *reinterpret_cast<const float4*>(Bp + (size_t)bk0       * A_ + bc);
        float4 b1v = *reinterpret_cast<const float4*>(Bp + (size_t)(bk0 + 8) * A_ + bc);
        *reinterpret_cast<float4*>(&Bs[0][bk0][bc])     = b0;
        *reinterpret_cast<float4*>(&Bs[0][bk0 + 8][bc]) = b1v;
    }
    __syncthreads();

    int buf = 0;
#pragma unroll 1
    for (int kt = 0; kt < D_ / BK; kt++) {
        float4 pa0, pa1, pb0, pb1;
        const bool more = (kt + 1) < (D_ / BK);
        if (more) {
            const int kn = (kt + 1) * BK;
            pa0 = *reinterpret_cast<const float4*>(Ap + (size_t)arow * D_        + kn + akq);
            pa1 = *reinterpret_cast<const float4*>(Ap + (size_t)(arow + 64) * D_ + kn + akq);
            pb0 = *reinterpret_cast<const float4*>(Bp + (size_t)(kn + bk0)     * A_ + bc);
            pb1 = *reinterpret_cast<const float4*>(Bp + (size_t)(kn + bk0 + 8) * A_ + bc);
        }
#pragma unroll
        for (int kk = 0; kk < BK; kk++) {
            float a[8], bfr[8];
            *reinterpret_cast<float4*>(&a[0])   = *reinterpret_cast<float4*>(&As[buf][kk][ty * 8]);
            *reinterpret_cast<float4*>(&a[4])   = *reinterpret_cast<float4*>(&As[buf][kk][ty * 8 + 4]);
            *reinterpret_cast<float4*>(&bfr[0]) = *reinterpret_cast<float4*>(&Bs[buf][kk][tx * 8]);
            *reinterpret_cast<float4*>(&bfr[4]) = *reinterpret_cast<float4*>(&Bs[buf][kk][tx * 8 + 4]);
#pragma unroll
            for (int i = 0; i < 8; i++)
#pragma unroll
                for (int j = 0; j < 8; j++)
                    acc[i][j] = fmaf(a[i], bfr[j], acc[i][j]);
        }
        if (more) {
            const int nb = buf ^ 1;
            As[nb][akq + 0][arow] = pa0.x; As[nb][akq + 1][arow] = pa0.y;
            As[nb][akq + 2][arow] = pa0.z; As[nb][akq + 3][arow] = pa0.w;
            As[nb][akq + 0][arow + 64] = pa1.x; As[nb][akq + 1][arow + 64] = pa1.y;
            As[nb][akq + 2][arow + 64] = pa1.z; As[nb][akq + 3][arow + 64] = pa1.w;
            *reinterpret_cast<float4*>(&Bs[nb][bk0][bc])     = pb0;
            *reinterpret_cast<float4*>(&Bs[nb][bk0 + 8][bc]) = pb1;
            __syncthreads();
            buf = nb;
        }
    }

    // epilogue: tanh, weight by v, reduce across the 8 cols of this thread
    float part[8];
#pragma unroll
    for (int i = 0; i < 8; i++) {
        float s = 0.f;
#pragma unroll
        for (int j = 0; j < 8; j++) {
            const int a = n0 + tx * 8 + j;
            const float z = acc[i][j] + __ldg(&b1[a]);
            s += __ldg(&v[a]) * tanhf(z);
        }
        part[i] = s;
    }
    // reduce across tx (16 lanes of a half-warp)
#pragma unroll
    for (int off = 8; off > 0; off >>= 1)
#pragma unroll
        for (int i = 0; i < 8; i++)
            part[i] += __shfl_down_sync(0xffffffffu, part[i], off, 16);

    if (tx == 0) {
#pragma unroll
        for (int i = 0; i < 8; i++)
            g_spart[(size_t)blockIdx.y * (B_ * S_) + m0 + ty * 8 + i] = part[i];
    }
}

// ==============================================================================
// K2-prep: per batch b — max, w = exp(s - max), inclusive prefix (Zp) and
// inclusive suffix (Zs) scans of w. One block of 1024 threads per batch.
// ==============================================================================
__global__ __launch_bounds__(1024)
void k_prep()
{
    const int b = blockIdx.x;
    const int t = threadIdx.x;
    const int lane = t & 31;
    const int warp = t >> 5;

    __shared__ float sh[S_];
    __shared__ float red[32];
    __shared__ float bmax;

    const int base = b * S_;
    float s = g_spart[base + t] + g_spart[B_ * S_ + base + t];

    // block max
    float m = s;
#pragma unroll
    for (int off = 16; off > 0; off >>= 1)
        m = fmaxf(m, __shfl_xor_sync(0xffffffffu, m, off));
    if (lane == 0) red[warp] = m;
    __syncthreads();
    if (t == 0) {
        float mm = red[0];
        for (int i = 1; i < 32; i++) mm = fmaxf(mm, red[i]);
        bmax = mm;
    }
    __syncthreads();

    const float w = expf(s - bmax);
    g_w[base + t] = w;
    sh[t] = w;
    __syncthreads();

    // ---- inclusive prefix scan of w ----
    float ps = w;
#pragma unroll
    for (int off = 1; off < 32; off <<= 1) {
        float n = __shfl_up_sync(0xffffffffu, ps, off);
        if (lane >= off) ps += n;
    }
    if (lane == 31) red[warp] = ps;
    __syncthreads();
    if (warp == 0) {
        float x = red[lane];
#pragma unroll
        for (int off = 1; off < 32; off <<= 1) {
            float n = __shfl_up_sync(0xffffffffu, x, off);
            if (lane >= off) x += n;
        }
        red[lane] = x;
    }
    __syncthreads();
    g_zp[base + t] = ps + (warp ? red[warp - 1] : 0.f);
    __syncthreads();

    // ---- inclusive suffix scan: prefix scan over reversed w ----
    float wr = sh[(S_ - 1) - t];
    float pr = wr;
#pragma unroll
    for (int off = 1; off < 32; off <<= 1) {
        float n = __shfl_up_sync(0xffffffffu, pr, off);
        if (lane >= off) pr += n;
    }
    if (lane == 31) red[warp] = pr;
    __syncthreads();
    if (warp == 0) {
        float x = red[lane];
#pragma unroll
        for (int off = 1; off < 32; off <<= 1) {
            float n = __shfl_up_sync(0xffffffffu, x, off);
            if (lane >= off) x += n;
        }
        red[lane] = x;
    }
    __syncthreads();
    g_zs[base + (S_ - 1) - t] = pr + (warp ? red[warp - 1] : 0.f);
}

// ==============================================================================
// K2-passA: segment partial sums  PS[b][seg][d] = sum_{l in seg} w[l]*h[b,l,d]
// grid (B, NSEG), 256 threads, float4 per thread covers all D=1024.
// ==============================================================================
__global__ __launch_bounds__(256)
void k_passA(const float* __restrict__ H)
{
    const int b   = blockIdx.x;
    const int seg = blockIdx.y;
    const int t   = threadIdx.x;
    const int d   = t * 4;

    __shared__ float ws[SEGL];
    if (t < SEGL) ws[t] = g_w[b * S_ + seg * SEGL + t];
    __syncthreads();

    const float* hp = H + ((size_t)b * S_ + seg * SEGL) * D_ + d;
    float4 acc = make_float4(0.f, 0.f, 0.f, 0.f);
#pragma unroll 8
    for (int l = 0; l < SEGL; l++) {
        float4 h4 = *reinterpret_cast<const float4*>(hp + (size_t)l * D_);
        acc = f4fma(ws[l], h4, acc);
    }
    *reinterpret_cast<float4*>(&g_ps[((size_t)b * NSEG + seg) * D_ + d]) = acc;
}

// ==============================================================================
// K2-passB: final pooled output.
//  pt==0 (prefix):  out[j,d] = P_j[d]            / (Zp_j       * (j+1))
//  pt==1 (postfix): out[j,d] = Sfx_j[d]          / (Zs_j       * (S-j))   (true suffix scan)
//  pt==2 (cloze):   out[j,d] = (T[d]-w_j h[j,d]) / ((Zt - w_j) * (S-1))
// grid (B, NSEG), 256 threads (float4 over D).
// ==============================================================================
__global__ __launch_bounds__(256)
void k_passB(const float* __restrict__ H, const int* __restrict__ pt_ids,
             float* __restrict__ out)
{
    const int b   = blockIdx.x;
    const int seg = blockIdx.y;
    const int t   = threadIdx.x;
    const int d   = t * 4;
    const int pt  = pt_ids[b];

    __shared__ float ws[SEGL], zps[SEGL], zss[SEGL];
    if (t < SEGL) {
        const int l = seg * SEGL + t;
        ws[t]  = g_w [b * S_ + l];
        zps[t] = g_zp[b * S_ + l];
        zss[t] = g_zs[b * S_ + l];
    }
    __syncthreads();

    const float ztot = g_zp[b * S_ + (S_ - 1)];

    // accumulate carries from other segments
    const float* psb = g_ps + (size_t)b * NSEG * D_ + d;
    float4 carry = make_float4(0.f, 0.f, 0.f, 0.f);
    float4 total = make_float4(0.f, 0.f, 0.f, 0.f);
#pragma unroll
    for (int s2 = 0; s2 < NSEG; s2++) {
        float4 p = *reinterpret_cast<const float4*>(psb + (size_t)s2 * D_);
        total = f4add(total, p);
        if (pt == 0) { if (s2 < seg) carry = f4add(carry, p); }
        else if (pt == 1) { if (s2 > seg) carry = f4add(carry, p); }
    }

    const float* hp = H   + ((size_t)b * S_ + seg * SEGL) * D_ + d;
    float*       op = out + ((size_t)b * S_ + seg * SEGL) * D_ + d;

    if (pt == 0) {
        float4 acc = carry;
#pragma unroll 4
        for (int i = 0; i < SEGL; i++) {
            const int j = seg * SEGL + i;
            float4 h4 = *reinterpret_cast<const float4*>(hp + (size_t)i * D_);
            acc = f4fma(ws[i], h4, acc);
            const float inv = 1.f / (zps[i] * (float)(j + 1));
            *reinterpret_cast<float4*>(op + (size_t)i * D_) = f4scale(acc, inv);
        }
    } else if (pt == 1) {
        float4 acc = carry;
#pragma unroll 4
        for (int i = SEGL - 1; i >= 0; i--) {
            const int j = seg * SEGL + i;
            float4 h4 = *reinterpret_cast<const float4*>(hp + (size_t)i * D_);
            acc = f4fma(ws[i], h4, acc);
            const float inv = 1.f / (zss[i] * (float)(S_ - j));
            *reinterpret_cast<float4*>(op + (size_t)i * D_) = f4scale(acc, inv);
        }
    } else {
        const float invcnt = 1.f / (float)(S_ - 1);
#pragma unroll 4
        for (int i = 0; i < SEGL; i++) {
            float4 h4 = *reinterpret_cast<const float4*>(hp + (size_t)i * D_);
            const float wl = ws[i];
            const float inv = invcnt / (ztot - wl);
            float4 num = f4fma(-wl, h4, total);
            *reinterpret_cast<float4*>(op + (size_t)i * D_) = f4scale(num, inv);
        }
    }
}

// ==============================================================================
extern "C" void kernel_launch(void* const* d_in, const int* in_sizes, int n_in,
                              void* d_out, int out_size)
{
    const float* H   = (const float*)d_in[0];
    const float* W1  = (const float*)d_in[1];
    const float* b1  = (const float*)d_in[2];
    const float* v   = (const float*)d_in[3];
    const int*   pt  = (const int*)  d_in[4];
    float*       out = (float*)d_out;

    k_scores<<<dim3((B_ * S_) / BM, A_ / BN), 256>>>(H, W1, b1, v);
    k_prep  <<<B_, S_>>>();
    k_passA <<<dim3(B_, NSEG), 256>>>(H);
    k_passB <<<dim3(B_, NSEG), 256>>>(H, pt, out);
}

// round 3
// speedup vs baseline: 2.1258x; 2.1258x over previous
#include <cuda_runtime.h>
#include <cuda_bf16.h>
#include <cstdint>

// Problem shape (fixed by dataset): B=16, S=1024, D=1024, A=256
#define B_    16
#define S_    1024
#define D_    1024
#define A_    256
#define NSEG  32
#define SEGL  32      // S_/NSEG

// ---------------- scratch (device globals; no allocation allowed) -------------
__device__ float g_s [B_ * S_];              // final attention scores
__device__ float g_w [B_ * S_];              // exp(s - max_b)
__device__ float g_zp[B_ * S_];              // inclusive prefix sum of w
__device__ float g_zs[B_ * S_];              // inclusive suffix sum of w
__device__ float g_ps[B_ * NSEG * D_];       // segment partial sums of w*h
// Pre-split, transposed (n-major), PRE-SWIZZLED W1: 16 K-chunks x 32KB (hi & lo)
__device__ uint4 g_Bhi[16 * 2048];
__device__ uint4 g_Blo[16 * 2048];

// ---------------- small float4 helpers ----------------------------------------
__device__ __forceinline__ float4 f4add(float4 a, float4 b) {
    return make_float4(a.x + b.x, a.y + b.y, a.z + b.z, a.w + b.w);
}
__device__ __forceinline__ float4 f4fma(float s, float4 h, float4 acc) {
    acc.x = fmaf(s, h.x, acc.x); acc.y = fmaf(s, h.y, acc.y);
    acc.z = fmaf(s, h.z, acc.z); acc.w = fmaf(s, h.w, acc.w);
    return acc;
}
__device__ __forceinline__ float4 f4scale(float4 a, float s) {
    return make_float4(a.x * s, a.y * s, a.z * s, a.w * s);
}

// ---------------- portable PTX helpers (sm_80-class; no 'a' features) ---------
__device__ __forceinline__ uint32_t smem_u32(const void* p) {
    uint32_t a;
    asm("{ .reg .u64 t; cvta.to.shared.u64 t, %1; cvt.u32.u64 %0, t; }" : "=r"(a) : "l"(p));
    return a;
}
__device__ __forceinline__ uint32_t bpack(__nv_bfloat16 a, __nv_bfloat16 b) {
    __nv_bfloat162 t; t.x = a; t.y = b;
    return *reinterpret_cast<uint32_t*>(&t);
}
__device__ __forceinline__ void ldsm_x4(uint32_t* r, uint32_t addr) {
    asm volatile("ldmatrix.sync.aligned.m8n8.x4.shared.b16 {%0,%1,%2,%3}, [%4];"
                 : "=r"(r[0]), "=r"(r[1]), "=r"(r[2]), "=r"(r[3]) : "r"(addr));
}
__device__ __forceinline__ void mma_bf16(float* c, const uint32_t* a, const uint32_t* b) {
    asm volatile(
        "mma.sync.aligned.m16n8k16.row.col.f32.bf16.bf16.f32 "
        "{%0,%1,%2,%3}, {%4,%5,%6,%7}, {%8,%9}, {%0,%1,%2,%3};"
        : "+f"(c[0]), "+f"(c[1]), "+f"(c[2]), "+f"(c[3])
        : "r"(a[0]), "r"(a[1]), "r"(a[2]), "r"(a[3]), "r"(b[0]), "r"(b[1]));
}
#define CP_ASYNC16(dst, src) \
    asm volatile("cp.async.cg.shared.global [%0], [%1], 16;" :: "r"(dst), "l"(src))
#define CP_COMMIT() asm volatile("cp.async.commit_group;" ::: "memory")
#define CP_WAIT0()  asm volatile("cp.async.wait_group 0;" ::: "memory")

#define SWZ(x) ((x) ^ (((x) >> 3) & 0x70))

// ==============================================================================
// k_splitB: W1 [K=1024][N=256] fp32 -> B^T [n][k] bf16 hi/lo, stored as 16
// pre-swizzled 32KB K64-chunk images (128B rows of 64 bf16 per n).
// ==============================================================================
__global__ __launch_bounds__(256)
void k_splitB(const float* __restrict__ W1)
{
    const int p  = blockIdx.x * 256 + threadIdx.x;   // 0..131071
    const int n  = p & 255;
    const int kp = p >> 8;                           // 0..511
    const int k  = kp * 2;
    const int c  = k >> 6;                           // K64 chunk
    const int kk = k & 63;

    const float x0 = W1[(size_t)k * A_ + n];
    const float x1 = W1[(size_t)(k + 1) * A_ + n];
    const __nv_bfloat16 h0 = __float2bfloat16_rn(x0);
    const __nv_bfloat16 h1 = __float2bfloat16_rn(x1);
    const __nv_bfloat16 l0 = __float2bfloat16_rn(x0 - __bfloat162float(h0));
    const __nv_bfloat16 l1 = __float2bfloat16_rn(x1 - __bfloat162float(h1));

    const uint32_t boff = (uint32_t)n * 128 + (uint32_t)kk * 2;
    const uint32_t sw   = SWZ(boff);
    *reinterpret_cast<uint32_t*>(reinterpret_cast<char*>(g_Bhi) + (size_t)c * 32768 + sw) = bpack(h0, h1);
    *reinterpret_cast<uint32_t*>(reinterpret_cast<char*>(g_Blo) + (size_t)c * 32768 + sw) = bpack(l0, l1);
}

// ==============================================================================
// k_scores_mma: bf16-split GEMM via mma.sync (portable HMMA path).
// CTA tile 64(M) x 256(N, full), BK=64, 8 warps (2M x 4N), warp tile 32x64.
// acc += Ahi*Bhi + Ahi*Blo + Alo*Bhi   (fp32 accum, ~1.5e-5 rel err)
// Epilogue: s[m] = sum_n v[n]*tanh(acc[m][n] + b1[n]) -> g_s
// ==============================================================================
#define OFF_V     0
#define OFF_B1    1024
#define OFF_DATA  4096
#define STAGE_SZ  81920      // Ahi 8K | Alo 8K | Bhi 32K | Blo 32K
#define SA_LO     8192
#define SB_HI     16384
#define SB_LO     49152
#define SMEM_BYTES (OFF_DATA + 2 * STAGE_SZ)   // 167936

__global__ __launch_bounds__(256, 1)
void k_scores_mma(const float* __restrict__ H, const float* __restrict__ b1,
                  const float* __restrict__ v)
{
    extern __shared__ char smem[];
    const uint32_t sb = smem_u32(smem);
    const int tid  = threadIdx.x;
    const int lane = tid & 31;
    const int wid  = tid >> 5;
    const int wm   = (wid & 1) * 32;       // warp M offset (0/32)
    const int wn   = (wid >> 1) * 64;      // warp N offset (0/64/128/192)
    const int m0   = blockIdx.x * 64;

    ((float*)(smem + OFF_V))[tid]  = v[tid];
    ((float*)(smem + OFF_B1))[tid] = b1[tid];

    // ---- A global load mapping: row = tid/4 (64 rows), 16 consecutive k floats
    const int arow = tid >> 2;
    const int acol = (tid & 3) * 16;
    const float4* Ag = reinterpret_cast<const float4*>(H + (size_t)(m0 + arow) * D_ + acol);
    const uint32_t a_sts_base = (uint32_t)arow * 128 + (uint32_t)acol * 2;

    // ---- ldmatrix lane offsets (bytes within tile) ----
    const int ar = lane & 15;
    const uint32_t a_kb = (uint32_t)(lane >> 4) * 16;
    uint32_t aoff[2];
#pragma unroll
    for (int mt = 0; mt < 2; mt++)
        aoff[mt] = (uint32_t)(wm + mt * 16 + ar) * 128 + a_kb;

    const int bn = (lane & 7) + ((lane >> 4) << 3);
    const uint32_t b_kb = (uint32_t)((lane >> 3) & 1) * 16;
    uint32_t boff[4];
#pragma unroll
    for (int np = 0; np < 4; np++)
        boff[np] = (uint32_t)(wn + np * 16 + bn) * 128 + b_kb;

    float acc[2][8][4];
#pragma unroll
    for (int mt = 0; mt < 2; mt++)
#pragma unroll
        for (int nt = 0; nt < 8; nt++)
#pragma unroll
            for (int e = 0; e < 4; e++) acc[mt][nt][e] = 0.f;

    // ---- prologue: fill stage 0 ----
    {
        const uint32_t st = sb + OFF_DATA;
#pragma unroll
        for (int u = 0; u < 8; u++) {
            CP_ASYNC16(st + SB_HI + (tid + u * 256) * 16, (const char*)(g_Bhi + tid + u * 256));
            CP_ASYNC16(st + SB_LO + (tid + u * 256) * 16, (const char*)(g_Blo + tid + u * 256));
        }
        CP_COMMIT();
        float4 a4[4];
#pragma unroll
        for (int i = 0; i < 4; i++) a4[i] = __ldg(Ag + i);
        uint32_t hi[8], lo[8];
#pragma unroll
        for (int i = 0; i < 4; i++) {
            __nv_bfloat16 hx = __float2bfloat16_rn(a4[i].x), hy = __float2bfloat16_rn(a4[i].y);
            __nv_bfloat16 hz = __float2bfloat16_rn(a4[i].z), hw = __float2bfloat16_rn(a4[i].w);
            hi[2*i]   = bpack(hx, hy);
            hi[2*i+1] = bpack(hz, hw);
            lo[2*i]   = bpack(__float2bfloat16_rn(a4[i].x - __bfloat162float(hx)),
                              __float2bfloat16_rn(a4[i].y - __bfloat162float(hy)));
            lo[2*i+1] = bpack(__float2bfloat16_rn(a4[i].z - __bfloat162float(hz)),
                              __float2bfloat16_rn(a4[i].w - __bfloat162float(hw)));
        }
#pragma unroll
        for (int q = 0; q < 2; q++) {
            const uint32_t sw = SWZ(a_sts_base + q * 16);
            *reinterpret_cast<uint4*>(smem + OFF_DATA + sw) =
                make_uint4(hi[4*q], hi[4*q+1], hi[4*q+2], hi[4*q+3]);
            *reinterpret_cast<uint4*>(smem + OFF_DATA + SA_LO + sw) =
                make_uint4(lo[4*q], lo[4*q+1], lo[4*q+2], lo[4*q+3]);
        }
        CP_WAIT0();
        __syncthreads();
    }

#pragma unroll 1
    for (int c = 0; c < 16; c++) {
        const uint32_t cur = sb + OFF_DATA + (uint32_t)(c & 1) * STAGE_SZ;
        const uint32_t nxt = sb + OFF_DATA + (uint32_t)((c + 1) & 1) * STAGE_SZ;
        const bool more = (c + 1) < 16;

        // prefetch next B via cp.async, next A via LDG
        float4 a4[4];
        if (more) {
#pragma unroll
            for (int u = 0; u < 8; u++) {
                CP_ASYNC16(nxt + SB_HI + (tid + u * 256) * 16,
                           (const char*)(g_Bhi + (c + 1) * 2048 + tid + u * 256));
                CP_ASYNC16(nxt + SB_LO + (tid + u * 256) * 16,
                           (const char*)(g_Blo + (c + 1) * 2048 + tid + u * 256));
            }
            CP_COMMIT();
#pragma unroll
            for (int i = 0; i < 4; i++) a4[i] = __ldg(Ag + (c + 1) * 16 + i);
        }

        // ---- compute from cur ----
#pragma unroll
        for (int ks = 0; ks < 4; ks++) {
            uint32_t ah[2][4], al[2][4];
#pragma unroll
            for (int mt = 0; mt < 2; mt++) {
                const uint32_t sw = SWZ(aoff[mt] + ks * 32);
                ldsm_x4(ah[mt], cur + sw);
                ldsm_x4(al[mt], cur + SA_LO + sw);
            }
            uint32_t bh[8][2], bl[8][2];
#pragma unroll
            for (int np = 0; np < 4; np++) {
                const uint32_t sw = SWZ(boff[np] + ks * 32);
                uint32_t r[4];
                ldsm_x4(r, cur + SB_HI + sw);
                bh[np*2][0] = r[0]; bh[np*2][1] = r[1];
                bh[np*2+1][0] = r[2]; bh[np*2+1][1] = r[3];
                ldsm_x4(r, cur + SB_LO + sw);
                bl[np*2][0] = r[0]; bl[np*2][1] = r[1];
                bl[np*2+1][0] = r[2]; bl[np*2+1][1] = r[3];
            }
#pragma unroll
            for (int mt = 0; mt < 2; mt++)
#pragma unroll
                for (int nt = 0; nt < 8; nt++) {
                    mma_bf16(acc[mt][nt], ah[mt], bh[nt]);
                    mma_bf16(acc[mt][nt], ah[mt], bl[nt]);
                    mma_bf16(acc[mt][nt], al[mt], bh[nt]);
                }
        }

        if (more) {
            uint32_t hi[8], lo[8];
#pragma unroll
            for (int i = 0; i < 4; i++) {
                __nv_bfloat16 hx = __float2bfloat16_rn(a4[i].x), hy = __float2bfloat16_rn(a4[i].y);
                __nv_bfloat16 hz = __float2bfloat16_rn(a4[i].z), hw = __float2bfloat16_rn(a4[i].w);
                hi[2*i]   = bpack(hx, hy);
                hi[2*i+1] = bpack(hz, hw);
                lo[2*i]   = bpack(__float2bfloat16_rn(a4[i].x - __bfloat162float(hx)),
                                  __float2bfloat16_rn(a4[i].y - __bfloat162float(hy)));
                lo[2*i+1] = bpack(__float2bfloat16_rn(a4[i].z - __bfloat162float(hz)),
                                  __float2bfloat16_rn(a4[i].w - __bfloat162float(hw)));
            }
            const uint32_t nxt_off = OFF_DATA + (uint32_t)((c + 1) & 1) * STAGE_SZ;
#pragma unroll
            for (int q = 0; q < 2; q++) {
                const uint32_t sw = SWZ(a_sts_base + q * 16);
                *reinterpret_cast<uint4*>(smem + nxt_off + sw) =
                    make_uint4(hi[4*q], hi[4*q+1], hi[4*q+2], hi[4*q+3]);
                *reinterpret_cast<uint4*>(smem + nxt_off + SA_LO + sw) =
                    make_uint4(lo[4*q], lo[4*q+1], lo[4*q+2], lo[4*q+3]);
            }
            CP_WAIT0();
            __syncthreads();
        }
    }
    __syncthreads();   // stage area about to be reused as reduction buffer

    // ---- epilogue: s[m] = sum_n v[n] * tanh(acc + b1[n]) ----
    {
        const float* vs  = (const float*)(smem + OFF_V);
        const float* b1s = (const float*)(smem + OFF_B1);
        float* red = (float*)(smem + OFF_DATA);   // [64][4]
        const int nw = wid >> 1;

#pragma unroll
        for (int mt = 0; mt < 2; mt++) {
            float s0 = 0.f, s1 = 0.f;
#pragma unroll
            for (int nt = 0; nt < 8; nt++) {
#pragma unroll
                for (int e = 0; e < 2; e++) {
                    const int col = wn + nt * 8 + (lane & 3) * 2 + e;
                    s0 = fmaf(vs[col], tanhf(acc[mt][nt][e]     + b1s[col]), s0);
                    s1 = fmaf(vs[col], tanhf(acc[mt][nt][e + 2] + b1s[col]), s1);
                }
            }
            s0 += __shfl_xor_sync(0xffffffffu, s0, 1);
            s0 += __shfl_xor_sync(0xffffffffu, s0, 2);
            s1 += __shfl_xor_sync(0xffffffffu, s1, 1);
            s1 += __shfl_xor_sync(0xffffffffu, s1, 2);
            if ((lane & 3) == 0) {
                const int r0 = wm + mt * 16 + (lane >> 2);
                red[r0 * 4 + nw]       = s0;
                red[(r0 + 8) * 4 + nw] = s1;
            }
        }
        __syncthreads();
        if (tid < 64) {
            const float s = red[tid * 4] + red[tid * 4 + 1] + red[tid * 4 + 2] + red[tid * 4 + 3];
            g_s[m0 + tid] = s;
        }
    }
}

// ==============================================================================
// K2-prep: per batch b — max, w = exp(s - max), inclusive prefix (Zp) and
// inclusive suffix (Zs) scans of w. One block of 1024 threads per batch.
// ==============================================================================
__global__ __launch_bounds__(1024)
void k_prep()
{
    const int b = blockIdx.x;
    const int t = threadIdx.x;
    const int lane = t & 31;
    const int warp = t >> 5;

    __shared__ float sh[S_];
    __shared__ float red[32];
    __shared__ float bmax;

    const int base = b * S_;
    float s = g_s[base + t];

    float m = s;
#pragma unroll
    for (int off = 16; off > 0; off >>= 1)
        m = fmaxf(m, __shfl_xor_sync(0xffffffffu, m, off));
    if (lane == 0) red[warp] = m;
    __syncthreads();
    if (t == 0) {
        float mm = red[0];
        for (int i = 1; i < 32; i++) mm = fmaxf(mm, red[i]);
        bmax = mm;
    }
    __syncthreads();

    const float w = expf(s - bmax);
    g_w[base + t] = w;
    sh[t] = w;
    __syncthreads();

    float ps = w;
#pragma unroll
    for (int off = 1; off < 32; off <<= 1) {
        float n = __shfl_up_sync(0xffffffffu, ps, off);
        if (lane >= off) ps += n;
    }
    if (lane == 31) red[warp] = ps;
    __syncthreads();
    if (warp == 0) {
        float x = red[lane];
#pragma unroll
        for (int off = 1; off < 32; off <<= 1) {
            float n = __shfl_up_sync(0xffffffffu, x, off);
            if (lane >= off) x += n;
        }
        red[lane] = x;
    }
    __syncthreads();
    g_zp[base + t] = ps + (warp ? red[warp - 1] : 0.f);
    __syncthreads();

    float wr = sh[(S_ - 1) - t];
    float pr = wr;
#pragma unroll
    for (int off = 1; off < 32; off <<= 1) {
        float n = __shfl_up_sync(0xffffffffu, pr, off);
        if (lane >= off) pr += n;
    }
    if (lane == 31) red[warp] = pr;
    __syncthreads();
    if (warp == 0) {
        float x = red[lane];
#pragma unroll
        for (int off = 1; off < 32; off <<= 1) {
            float n = __shfl_up_sync(0xffffffffu, x, off);
            if (lane >= off) x += n;
        }
        red[lane] = x;
    }
    __syncthreads();
    g_zs[base + (S_ - 1) - t] = pr + (warp ? red[warp - 1] : 0.f);
}

// ==============================================================================
// K2-passA: segment partial sums  PS[b][seg][d] = sum_{l in seg} w[l]*h[b,l,d]
// ==============================================================================
__global__ __launch_bounds__(256)
void k_passA(const float* __restrict__ H)
{
    const int b   = blockIdx.x;
    const int seg = blockIdx.y;
    const int t   = threadIdx.x;
    const int d   = t * 4;

    __shared__ float ws[SEGL];
    if (t < SEGL) ws[t] = g_w[b * S_ + seg * SEGL + t];
    __syncthreads();

    const float* hp = H + ((size_t)b * S_ + seg * SEGL) * D_ + d;
    float4 acc = make_float4(0.f, 0.f, 0.f, 0.f);
#pragma unroll 8
    for (int l = 0; l < SEGL; l++) {
        float4 h4 = *reinterpret_cast<const float4*>(hp + (size_t)l * D_);
        acc = f4fma(ws[l], h4, acc);
    }
    *reinterpret_cast<float4*>(&g_ps[((size_t)b * NSEG + seg) * D_ + d]) = acc;
}

// ==============================================================================
// K2-passB: final pooled output.
//  pt==0 (prefix):  out[j,d] = P_j[d]            / (Zp_j       * (j+1))
//  pt==1 (postfix): out[j,d] = Sfx_j[d]          / (Zs_j       * (S-j))
//  pt==2 (cloze):   out[j,d] = (T[d]-w_j h[j,d]) / ((Zt - w_j) * (S-1))
// ==============================================================================
__global__ __launch_bounds__(256)
void k_passB(const float* __restrict__ H, const int* __restrict__ pt_ids,
             float* __restrict__ out)
{
    const int b   = blockIdx.x;
    const int seg = blockIdx.y;
    const int t   = threadIdx.x;
    const int d   = t * 4;
    const int pt  = pt_ids[b];

    __shared__ float ws[SEGL], zps[SEGL], zss[SEGL];
    if (t < SEGL) {
        const int l = seg * SEGL + t;
        ws[t]  = g_w [b * S_ + l];
        zps[t] = g_zp[b * S_ + l];
        zss[t] = g_zs[b * S_ + l];
    }
    __syncthreads();

    const float ztot = g_zp[b * S_ + (S_ - 1)];

    const float* psb = g_ps + (size_t)b * NSEG * D_ + d;
    float4 carry = make_float4(0.f, 0.f, 0.f, 0.f);
    float4 total = make_float4(0.f, 0.f, 0.f, 0.f);
#pragma unroll
    for (int s2 = 0; s2 < NSEG; s2++) {
        float4 p = *reinterpret_cast<const float4*>(psb + (size_t)s2 * D_);
        total = f4add(total, p);
        if (pt == 0) { if (s2 < seg) carry = f4add(carry, p); }
        else if (pt == 1) { if (s2 > seg) carry = f4add(carry, p); }
    }

    const float* hp = H   + ((size_t)b * S_ + seg * SEGL) * D_ + d;
    float*       op = out + ((size_t)b * S_ + seg * SEGL) * D_ + d;

    if (pt == 0) {
        float4 acc = carry;
#pragma unroll 4
        for (int i = 0; i < SEGL; i++) {
            const int j = seg * SEGL + i;
            float4 h4 = *reinterpret_cast<const float4*>(hp + (size_t)i * D_);
            acc = f4fma(ws[i], h4, acc);
            const float inv = 1.f / (zps[i] * (float)(j + 1));
            *reinterpret_cast<float4*>(op + (size_t)i * D_) = f4scale(acc, inv);
        }
    } else if (pt == 1) {
        float4 acc = carry;
#pragma unroll 4
        for (int i = SEGL - 1; i >= 0; i--) {
            const int j = seg * SEGL + i;
            float4 h4 = *reinterpret_cast<const float4*>(hp + (size_t)i * D_);
            acc = f4fma(ws[i], h4, acc);
            const float inv = 1.f / (zss[i] * (float)(S_ - j));
            *reinterpret_cast<float4*>(op + (size_t)i * D_) = f4scale(acc, inv);
        }
    } else {
        const float invcnt = 1.f / (float)(S_ - 1);
#pragma unroll 4
        for (int i = 0; i < SEGL; i++) {
            float4 h4 = *reinterpret_cast<const float4*>(hp + (size_t)i * D_);
            const float wl = ws[i];
            const float inv = invcnt / (ztot - wl);
            float4 num = f4fma(-wl, h4, total);
            *reinterpret_cast<float4*>(op + (size_t)i * D_) = f4scale(num, inv);
        }
    }
}

// ==============================================================================
extern "C" void kernel_launch(void* const* d_in, const int* in_sizes, int n_in,
                              void* d_out, int out_size)
{
    const float* H   = (const float*)d_in[0];
    const float* W1  = (const float*)d_in[1];
    const float* b1  = (const float*)d_in[2];
    const float* v   = (const float*)d_in[3];
    const int*   pt  = (const int*)  d_in[4];
    float*       out = (float*)d_out;

    cudaFuncSetAttribute(k_scores_mma, cudaFuncAttributeMaxDynamicSharedMemorySize, SMEM_BYTES);

    k_splitB    <<<512, 256>>>(W1);
    k_scores_mma<<<(B_ * S_) / 64, 256, SMEM_BYTES>>>(H, b1, v);
    k_prep      <<<B_, S_>>>();
    k_passA     <<<dim3(B_, NSEG), 256>>>(H);
    k_passB     <<<dim3(B_, NSEG), 256>>>(H, pt, out);
}